// round 1
// baseline (speedup 1.0000x reference)
#include <cuda_runtime.h>
#include <math.h>

#define T_ 256
#define B_ 128
#define I_ 1024
#define H_ 1024
#define P_ 512
#define G_ 4096  /* 4*H */

// ---------------- scratch (static device globals; no allocation) ----------------
__device__ float g_xg[(size_t)T_ * B_ * G_];   // [T*B, 4H] precomputed input gates (512 MB)
__device__ float g_h[B_ * P_];                 // recurrent h state [B,P]
__device__ float g_c[B_ * H_];                 // cell state [B,H]
__device__ float g_hfull[B_ * H_];             // o*tanh(c) before projection [B,H]

// ---------------- init / finalize ----------------
__global__ void init_state_kernel(const float* __restrict__ h0, const float* __restrict__ c0) {
    int i = blockIdx.x * blockDim.x + threadIdx.x;
    if (i < B_ * P_) g_h[i] = h0[i];
    if (i < B_ * H_) g_c[i] = c0[i];
}

__global__ void finalize_kernel(float* __restrict__ out) {
    int i = blockIdx.x * blockDim.x + threadIdx.x;
    const size_t ys_elems = (size_t)T_ * B_ * P_;
    if (i < B_ * P_) out[ys_elems + i] = g_h[i];
    if (i < B_ * H_) out[ys_elems + B_ * P_ + i] = g_c[i];
}

// ---------------- big GEMM: g_xg[M,N] = x[M,K] * W_ih[N,K]^T ----------------
// M = T*B = 32768, N = 4H = 4096, K = I = 1024. 128x128 tile, BK=8, 256 thr, 8x8/thread.
__global__ __launch_bounds__(256) void sgemm_xg_kernel(const float* __restrict__ A,
                                                       const float* __restrict__ Bm) {
    const int M = T_ * B_, N = G_, K = I_;
    __shared__ float As[8][128];
    __shared__ float Bs[8][128];

    const int bm = blockIdx.y * 128;
    const int bn = blockIdx.x * 128;
    const int tid = threadIdx.x;
    const int tx = tid & 15;
    const int ty = tid >> 4;
    const int lr = tid >> 1;           // 0..127: tile row
    const int lk = (tid & 1) << 2;     // 0 or 4

    float acc[8][8];
#pragma unroll
    for (int i = 0; i < 8; i++)
#pragma unroll
        for (int j = 0; j < 8; j++) acc[i][j] = 0.0f;

    const float* Ab = A + (size_t)bm * K;
    const float* Bb = Bm + (size_t)bn * K;

    for (int k0 = 0; k0 < K; k0 += 8) {
        float4 av = *(const float4*)(Ab + (size_t)lr * K + k0 + lk);
        float4 bv = *(const float4*)(Bb + (size_t)lr * K + k0 + lk);
        As[lk + 0][lr] = av.x; As[lk + 1][lr] = av.y; As[lk + 2][lr] = av.z; As[lk + 3][lr] = av.w;
        Bs[lk + 0][lr] = bv.x; Bs[lk + 1][lr] = bv.y; Bs[lk + 2][lr] = bv.z; Bs[lk + 3][lr] = bv.w;
        __syncthreads();
#pragma unroll
        for (int k = 0; k < 8; k++) {
            float ar[8], br[8];
            *(float4*)&ar[0] = *(const float4*)&As[k][ty * 8];
            *(float4*)&ar[4] = *(const float4*)&As[k][ty * 8 + 4];
            *(float4*)&br[0] = *(const float4*)&Bs[k][tx * 8];
            *(float4*)&br[4] = *(const float4*)&Bs[k][tx * 8 + 4];
#pragma unroll
            for (int i = 0; i < 8; i++)
#pragma unroll
                for (int j = 0; j < 8; j++) acc[i][j] += ar[i] * br[j];
        }
        __syncthreads();
    }

    float* Cb = g_xg + (size_t)(bm + ty * 8) * N + bn + tx * 8;
#pragma unroll
    for (int i = 0; i < 8; i++) {
        *(float4*)(Cb + (size_t)i * N)     = make_float4(acc[i][0], acc[i][1], acc[i][2], acc[i][3]);
        *(float4*)(Cb + (size_t)i * N + 4) = make_float4(acc[i][4], acc[i][5], acc[i][6], acc[i][7]);
    }
}

// ---------------- per-step fused gates GEMM + activations + cell update ----------------
// Computes, for tile (m0:m0+32, h0:h0+32) and ALL 4 gates:
//   gate[g] = xg[t] + g_h @ W_hh^T   (K = P = 512)
// then i,f,o=sigmoid, g=tanh; c = f*c + i*g; hfull = o*tanh(c).
__global__ __launch_bounds__(256) void gates_step_kernel(const float* __restrict__ Whh, int t) {
    __shared__ float As[8][32];        // h-state tile (transposed)
    __shared__ float Bs[4][8][32];     // 4 gate weight tiles

    const int m0 = blockIdx.y * 32;
    const int h0 = blockIdx.x * 32;
    const int tid = threadIdx.x;
    const int r = tid >> 3;            // 0..31
    const int kk = tid & 7;            // 0..7
    const int tx = tid & 15;
    const int ty = tid >> 4;

    float acc[4][2][2];
#pragma unroll
    for (int gg = 0; gg < 4; gg++)
#pragma unroll
        for (int a = 0; a < 2; a++)
#pragma unroll
            for (int b = 0; b < 2; b++) acc[gg][a][b] = 0.0f;

    for (int k0 = 0; k0 < P_; k0 += 8) {
        As[kk][r] = g_h[(m0 + r) * P_ + k0 + kk];
#pragma unroll
        for (int gg = 0; gg < 4; gg++)
            Bs[gg][kk][r] = Whh[(size_t)(gg * H_ + h0 + r) * P_ + k0 + kk];
        __syncthreads();
#pragma unroll
        for (int k = 0; k < 8; k++) {
            float a0 = As[k][ty * 2];
            float a1 = As[k][ty * 2 + 1];
#pragma unroll
            for (int gg = 0; gg < 4; gg++) {
                float b0 = Bs[gg][k][tx * 2];
                float b1 = Bs[gg][k][tx * 2 + 1];
                acc[gg][0][0] += a0 * b0;
                acc[gg][0][1] += a0 * b1;
                acc[gg][1][0] += a1 * b0;
                acc[gg][1][1] += a1 * b1;
            }
        }
        __syncthreads();
    }

    const float* xg_t = g_xg + (size_t)t * B_ * G_;
#pragma unroll
    for (int mi = 0; mi < 2; mi++) {
#pragma unroll
        for (int hi = 0; hi < 2; hi++) {
            int m = m0 + ty * 2 + mi;
            int hc = h0 + tx * 2 + hi;
            const float* xr = xg_t + (size_t)m * G_;
            float iv = acc[0][mi][hi] + xr[hc];
            float fv = acc[1][mi][hi] + xr[H_ + hc];
            float gv = acc[2][mi][hi] + xr[2 * H_ + hc];
            float ov = acc[3][mi][hi] + xr[3 * H_ + hc];
            iv = 1.0f / (1.0f + expf(-iv));
            fv = 1.0f / (1.0f + expf(-fv));
            gv = tanhf(gv);
            ov = 1.0f / (1.0f + expf(-ov));
            float cn = fv * g_c[m * H_ + hc] + iv * gv;
            g_c[m * H_ + hc] = cn;
            g_hfull[m * H_ + hc] = ov * tanhf(cn);
        }
    }
}

// ---------------- per-step projection: h_new[B,P] = hfull[B,H] @ W_hr[P,H]^T ----------------
// Writes both ys[t] (into d_out) and the recurrent h state.
__global__ __launch_bounds__(256) void proj_step_kernel(const float* __restrict__ Whr,
                                                        float* __restrict__ ys_t) {
    __shared__ float As[8][32];
    __shared__ float Bs[8][32];

    const int m0 = blockIdx.y * 32;
    const int n0 = blockIdx.x * 32;
    const int tid = threadIdx.x;
    const int r = tid >> 3;
    const int kk = tid & 7;
    const int tx = tid & 15;
    const int ty = tid >> 4;

    float acc[2][2] = {{0.0f, 0.0f}, {0.0f, 0.0f}};

    for (int k0 = 0; k0 < H_; k0 += 8) {
        As[kk][r] = g_hfull[(m0 + r) * H_ + k0 + kk];
        Bs[kk][r] = Whr[(size_t)(n0 + r) * H_ + k0 + kk];
        __syncthreads();
#pragma unroll
        for (int k = 0; k < 8; k++) {
            float a0 = As[k][ty * 2];
            float a1 = As[k][ty * 2 + 1];
            float b0 = Bs[k][tx * 2];
            float b1 = Bs[k][tx * 2 + 1];
            acc[0][0] += a0 * b0;
            acc[0][1] += a0 * b1;
            acc[1][0] += a1 * b0;
            acc[1][1] += a1 * b1;
        }
        __syncthreads();
    }

#pragma unroll
    for (int mi = 0; mi < 2; mi++) {
#pragma unroll
        for (int ni = 0; ni < 2; ni++) {
            int m = m0 + ty * 2 + mi;
            int n = n0 + tx * 2 + ni;
            float v = acc[mi][ni];
            ys_t[(size_t)m * P_ + n] = v;
            g_h[m * P_ + n] = v;
        }
    }
}

// ---------------- launch ----------------
extern "C" void kernel_launch(void* const* d_in, const int* in_sizes, int n_in,
                              void* d_out, int out_size) {
    const float* x   = (const float*)d_in[0];   // [T,B,I]
    const float* h0  = (const float*)d_in[1];   // [1,B,P]
    const float* c0  = (const float*)d_in[2];   // [1,B,H]
    const float* Wih = (const float*)d_in[3];   // [4H,I]
    const float* Whh = (const float*)d_in[4];   // [4H,P]
    const float* Whr = (const float*)d_in[5];   // [P,H]
    float* out = (float*)d_out;                 // [ys | hT | cT]

    // init recurrent state
    init_state_kernel<<<(B_ * H_ + 255) / 256, 256>>>(h0, c0);

    // xg = x @ W_ih^T for all timesteps
    dim3 gx(G_ / 128, (T_ * B_) / 128);
    sgemm_xg_kernel<<<gx, 256>>>(x, Wih);

    // sequential recurrence
    dim3 gg(H_ / 32, B_ / 32);   // 32 x 4 = 128 blocks
    dim3 gp(P_ / 32, B_ / 32);   // 16 x 4 = 64 blocks
    for (int t = 0; t < T_; t++) {
        gates_step_kernel<<<gg, 256>>>(Whh, t);
        proj_step_kernel<<<gp, 256>>>(Whr, out + (size_t)t * B_ * P_);
    }

    // append hT, cT
    finalize_kernel<<<(B_ * H_ + 255) / 256, 256>>>(out);
}

// round 2
// speedup vs baseline: 2.4046x; 2.4046x over previous
#include <cuda_runtime.h>
#include <math.h>

#define T_ 256
#define B_ 128
#define I_ 1024
#define H_ 1024
#define P_ 512
#define G_ 4096  /* 4*H */

// ---------------- scratch (static device globals; no allocation) ----------------
__device__ float g_xg[(size_t)T_ * B_ * G_];   // [T*B, 4H] precomputed input gates
__device__ float g_h[B_ * P_];                 // recurrent h state [B,P]
__device__ float g_c[B_ * H_];                 // cell state [B,H]
__device__ float g_hfull[B_ * H_];             // o*tanh(c) before projection [B,H]
__device__ float g_pp[4 * B_ * P_];            // proj split-K partials

// ---------------- helpers ----------------
__device__ __forceinline__ unsigned f2tf(float x) {
    unsigned r;
    asm("cvt.rna.tf32.f32 %0, %1;" : "=r"(r) : "f"(x));
    return r;
}

__device__ __forceinline__ void mma_tf32(float* c, const unsigned* a, const unsigned* b) {
    asm volatile(
        "mma.sync.aligned.m16n8k8.row.col.f32.tf32.tf32.f32 "
        "{%0,%1,%2,%3},{%4,%5,%6,%7},{%8,%9},{%0,%1,%2,%3};"
        : "+f"(c[0]), "+f"(c[1]), "+f"(c[2]), "+f"(c[3])
        : "r"(a[0]), "r"(a[1]), "r"(a[2]), "r"(a[3]), "r"(b[0]), "r"(b[1]));
}

__device__ __forceinline__ float sigmoidf_(float x) { return 1.0f / (1.0f + expf(-x)); }

// ---------------- init / finalize ----------------
__global__ void init_state_kernel(const float* __restrict__ h0, const float* __restrict__ c0) {
    int i = blockIdx.x * blockDim.x + threadIdx.x;
    if (i < B_ * P_) g_h[i] = h0[i];
    if (i < B_ * H_) g_c[i] = c0[i];
}

__global__ void finalize_kernel(float* __restrict__ out) {
    int i = blockIdx.x * blockDim.x + threadIdx.x;
    const size_t ys_elems = (size_t)T_ * B_ * P_;
    if (i < B_ * P_) out[ys_elems + i] = g_h[i];
    if (i < B_ * H_) out[ys_elems + B_ * P_ + i] = g_c[i];
}

// ---------------- xg = x @ W_ih^T via TF32 mma ----------------
// M=32768, N=4096, K=1024. BM=128, BN=128, BK=16, 256 thr (8 warps 2x4), warp 64x32.
#define XPAD 8
__global__ __launch_bounds__(256) void xg_mma_kernel(const float* __restrict__ X,
                                                     const float* __restrict__ Wih) {
    const int K = I_, N = G_;
    __shared__ unsigned As[16][128 + XPAD];
    __shared__ unsigned Bs[16][128 + XPAD];

    const int bm = blockIdx.y * 128;
    const int bn = blockIdx.x * 128;
    const int tid = threadIdx.x;
    const int lane = tid & 31, wid = tid >> 5;
    const int wm = (wid >> 2) * 64, wn = (wid & 3) * 32;
    const int g = lane >> 2, c = lane & 3;

    float acc[4][4][4];
#pragma unroll
    for (int i = 0; i < 4; i++)
#pragma unroll
        for (int j = 0; j < 4; j++)
#pragma unroll
            for (int r = 0; r < 4; r++) acc[i][j][r] = 0.0f;

    for (int k0 = 0; k0 < K; k0 += 16) {
#pragma unroll
        for (int it = 0; it < 2; it++) {
            int idx = it * 256 + tid;         // 0..511
            int row = idx >> 2;
            int kq = (idx & 3) * 4;
            float4 va = *(const float4*)(X + (size_t)(bm + row) * K + k0 + kq);
            As[kq + 0][row] = f2tf(va.x); As[kq + 1][row] = f2tf(va.y);
            As[kq + 2][row] = f2tf(va.z); As[kq + 3][row] = f2tf(va.w);
            float4 vb = *(const float4*)(Wih + (size_t)(bn + row) * K + k0 + kq);
            Bs[kq + 0][row] = f2tf(vb.x); Bs[kq + 1][row] = f2tf(vb.y);
            Bs[kq + 2][row] = f2tf(vb.z); Bs[kq + 3][row] = f2tf(vb.w);
        }
        __syncthreads();
#pragma unroll
        for (int kk = 0; kk < 16; kk += 8) {
            unsigned a[4][4], b[4][2];
#pragma unroll
            for (int i = 0; i < 4; i++) {
                int m = wm + i * 16;
                a[i][0] = As[kk + c][m + g];
                a[i][1] = As[kk + c][m + g + 8];
                a[i][2] = As[kk + c + 4][m + g];
                a[i][3] = As[kk + c + 4][m + g + 8];
            }
#pragma unroll
            for (int j = 0; j < 4; j++) {
                int n = wn + j * 8;
                b[j][0] = Bs[kk + c][n + g];
                b[j][1] = Bs[kk + 4 + c][n + g];
            }
#pragma unroll
            for (int i = 0; i < 4; i++)
#pragma unroll
                for (int j = 0; j < 4; j++) mma_tf32(acc[i][j], a[i], b[j]);
        }
        __syncthreads();
    }

#pragma unroll
    for (int i = 0; i < 4; i++) {
        int r0 = bm + wm + i * 16 + g;
#pragma unroll
        for (int j = 0; j < 4; j++) {
            int cc = bn + wn + j * 8 + c * 2;
            *(float2*)(g_xg + (size_t)r0 * N + cc)       = make_float2(acc[i][j][0], acc[i][j][1]);
            *(float2*)(g_xg + (size_t)(r0 + 8) * N + cc) = make_float2(acc[i][j][2], acc[i][j][3]);
        }
    }
}

// ---------------- fused gates mma + activations + cell update ----------------
// Block: all 128 batch rows x (4 gates x 8 h-cols). Grid = 128 blocks (hc tiles).
// B tile rows gathered as Whh[gate*1024 + hc]; n8-tile j == gate j, so each lane
// holds i,f,g,o for the same (m,hc) in registers -> fused epilogue.
__global__ __launch_bounds__(256) void gates_mma_kernel(const float* __restrict__ Whh, int t) {
    __shared__ unsigned As[16][128 + XPAD];
    __shared__ unsigned Bsm[16][32 + XPAD];

    const int hc0 = blockIdx.x * 8;
    const int tid = threadIdx.x;
    const int lane = tid & 31, wid = tid >> 5;
    const int g = lane >> 2, c = lane & 3;

    float acc[4][4];
#pragma unroll
    for (int j = 0; j < 4; j++)
#pragma unroll
        for (int r = 0; r < 4; r++) acc[j][r] = 0.0f;

    for (int k0 = 0; k0 < P_; k0 += 16) {
#pragma unroll
        for (int it = 0; it < 2; it++) {
            int idx = it * 256 + tid;
            int row = idx >> 2;
            int kq = (idx & 3) * 4;
            float4 va = *(const float4*)(g_h + (size_t)row * P_ + k0 + kq);
            As[kq + 0][row] = f2tf(va.x); As[kq + 1][row] = f2tf(va.y);
            As[kq + 2][row] = f2tf(va.z); As[kq + 3][row] = f2tf(va.w);
        }
        if (tid < 128) {
            int nl = tid >> 2;                 // 0..31
            int kq = (tid & 3) * 4;
            int wr = (nl >> 3) * H_ + hc0 + (nl & 7);   // gate*1024 + hc
            float4 vb = *(const float4*)(Whh + (size_t)wr * P_ + k0 + kq);
            Bsm[kq + 0][nl] = f2tf(vb.x); Bsm[kq + 1][nl] = f2tf(vb.y);
            Bsm[kq + 2][nl] = f2tf(vb.z); Bsm[kq + 3][nl] = f2tf(vb.w);
        }
        __syncthreads();
#pragma unroll
        for (int kk = 0; kk < 16; kk += 8) {
            unsigned a[4], b[4][2];
            int m = wid * 16;
            a[0] = As[kk + c][m + g];
            a[1] = As[kk + c][m + g + 8];
            a[2] = As[kk + c + 4][m + g];
            a[3] = As[kk + c + 4][m + g + 8];
#pragma unroll
            for (int j = 0; j < 4; j++) {
                b[j][0] = Bsm[kk + c][j * 8 + g];
                b[j][1] = Bsm[kk + 4 + c][j * 8 + g];
            }
#pragma unroll
            for (int j = 0; j < 4; j++) mma_tf32(acc[j], a, b[j]);
        }
        __syncthreads();
    }

    // fused epilogue: per lane 2 rows x 2 cols, all 4 gates in registers
    const float* xgp = g_xg + (size_t)t * B_ * G_;
    const int m_lo = wid * 16 + g;
    const int hc_base = hc0 + c * 2;
#pragma unroll
    for (int rr = 0; rr < 2; rr++) {
        int m = m_lo + rr * 8;
        const float* xr = xgp + (size_t)m * G_;
#pragma unroll
        for (int cc = 0; cc < 2; cc++) {
            int hc = hc_base + cc;
            int ai = rr * 2 + cc;
            float iv = acc[0][ai] + xr[hc];
            float fv = acc[1][ai] + xr[H_ + hc];
            float gv = acc[2][ai] + xr[2 * H_ + hc];
            float ov = acc[3][ai] + xr[3 * H_ + hc];
            iv = sigmoidf_(iv);
            fv = sigmoidf_(fv);
            gv = tanhf(gv);
            ov = sigmoidf_(ov);
            float cn = fv * g_c[m * H_ + hc] + iv * gv;
            g_c[m * H_ + hc] = cn;
            g_hfull[m * H_ + hc] = ov * tanhf(cn);
        }
    }
}

// ---------------- projection (fp32, split-K4): partials = hfull @ W_hr^T ----------------
// grid (8 n-tiles, 4 m-tiles, 4 splits) = 128 blocks, 128 thr, tile 32m x 64n, 4x4/thread.
__global__ __launch_bounds__(128) void proj_partial_kernel(const float* __restrict__ Whr) {
    __shared__ float As[8][32 + 2];
    __shared__ float Bs[8][64 + 2];

    const int m0 = blockIdx.y * 32;
    const int n0 = blockIdx.x * 64;
    const int kb = blockIdx.z * 256;
    const int tid = threadIdx.x;
    const int tx = tid & 15, ty = tid >> 4;

    float acc[4][4];
#pragma unroll
    for (int i = 0; i < 4; i++)
#pragma unroll
        for (int j = 0; j < 4; j++) acc[i][j] = 0.0f;

    for (int kc = 0; kc < 256; kc += 8) {
        int k0 = kb + kc;
        if (tid < 64) {
            int row = tid >> 1, kq = (tid & 1) * 4;
            float4 v = *(const float4*)(g_hfull + (size_t)(m0 + row) * H_ + k0 + kq);
            As[kq + 0][row] = v.x; As[kq + 1][row] = v.y; As[kq + 2][row] = v.z; As[kq + 3][row] = v.w;
        }
        {
            int row = tid >> 1, kq = (tid & 1) * 4;
            float4 v = *(const float4*)(Whr + (size_t)(n0 + row) * H_ + k0 + kq);
            Bs[kq + 0][row] = v.x; Bs[kq + 1][row] = v.y; Bs[kq + 2][row] = v.z; Bs[kq + 3][row] = v.w;
        }
        __syncthreads();
#pragma unroll
        for (int k = 0; k < 8; k++) {
            float a[4], b[4];
#pragma unroll
            for (int i = 0; i < 4; i++) a[i] = As[k][ty * 4 + i];
#pragma unroll
            for (int j = 0; j < 4; j++) b[j] = Bs[k][tx * 4 + j];
#pragma unroll
            for (int i = 0; i < 4; i++)
#pragma unroll
                for (int j = 0; j < 4; j++) acc[i][j] += a[i] * b[j];
        }
        __syncthreads();
    }

    float* pp = g_pp + (size_t)blockIdx.z * B_ * P_;
#pragma unroll
    for (int i = 0; i < 4; i++) {
        int m = m0 + ty * 4 + i;
        *(float4*)(pp + (size_t)m * P_ + n0 + tx * 4) =
            make_float4(acc[i][0], acc[i][1], acc[i][2], acc[i][3]);
    }
}

__global__ void combine_kernel(float* __restrict__ ys_t) {
    int i = blockIdx.x * blockDim.x + threadIdx.x;
    const int BP = B_ * P_;
    if (i < BP) {
        float v = g_pp[i] + g_pp[i + BP] + g_pp[i + 2 * BP] + g_pp[i + 3 * BP];
        ys_t[i] = v;
        g_h[i] = v;
    }
}

// ---------------- launch ----------------
extern "C" void kernel_launch(void* const* d_in, const int* in_sizes, int n_in,
                              void* d_out, int out_size) {
    const float* x   = (const float*)d_in[0];   // [T,B,I]
    const float* h0  = (const float*)d_in[1];   // [1,B,P]
    const float* c0  = (const float*)d_in[2];   // [1,B,H]
    const float* Wih = (const float*)d_in[3];   // [4H,I]
    const float* Whh = (const float*)d_in[4];   // [4H,P]
    const float* Whr = (const float*)d_in[5];   // [P,H]
    float* out = (float*)d_out;                 // [ys | hT | cT]

    init_state_kernel<<<(B_ * H_ + 255) / 256, 256>>>(h0, c0);

    // xg = x @ W_ih^T (TF32 tensor cores)
    dim3 gx(G_ / 128, (T_ * B_) / 128);
    xg_mma_kernel<<<gx, 256>>>(x, Wih);

    dim3 gp(P_ / 64, B_ / 32, 4);
    for (int t = 0; t < T_; t++) {
        gates_mma_kernel<<<128, 256>>>(Whh, t);
        proj_partial_kernel<<<gp, 128>>>(Whr);
        combine_kernel<<<(B_ * P_ + 255) / 256, 256>>>(out + (size_t)t * B_ * P_);
    }

    finalize_kernel<<<(B_ * H_ + 255) / 256, 256>>>(out);
}

// round 3
// speedup vs baseline: 4.1680x; 1.7333x over previous
#include <cuda_runtime.h>
#include <math.h>

#define T_ 256
#define B_ 128
#define I_ 1024
#define H_ 1024
#define P_ 512
#define G_ 4096  /* 4*H */

#define NBLK 128
#define NTHR 256
#define PROJ_BLKS 64

// persistent-kernel shared memory layout (32-bit words)
#define WHH_S 524    /* 512 + 12 : 12 mod 32 -> conflict-free b-frag reads */
#define WHR_S 1036   /* 1024 + 12 */
#define AS_S  76     /* 64 + 12  : m-major staging, conflict-free a-frag reads */
#define OFF_WHH 0
#define OFF_WHR (32 * WHH_S)                  /* 16768 */
#define OFF_AS  (OFF_WHR + 16 * WHR_S)        /* 33344 (16B aligned in bytes) */
#define OFF_C   (OFF_AS + 128 * AS_S)         /* 43072 */
#define SMEM_WORDS (OFF_C + 1024)             /* 44096 words = 176384 B */

// ---------------- globals (no allocation) ----------------
__device__ float g_xg[(size_t)T_ * B_ * G_];   // [T*B, 4H]
__device__ float g_h[B_ * P_];                 // recurrent h [B,P]
__device__ float g_hfull[B_ * H_];             // o*tanh(c) [B,H]
__device__ unsigned g_count;
__device__ unsigned g_release;

// ---------------- helpers ----------------
__device__ __forceinline__ unsigned f2tf(float x) {
    unsigned r;
    asm("cvt.rna.tf32.f32 %0, %1;" : "=r"(r) : "f"(x));
    return r;
}

__device__ __forceinline__ void mma_tf32(float* c, const unsigned* a, const unsigned* b) {
    asm volatile(
        "mma.sync.aligned.m16n8k8.row.col.f32.tf32.tf32.f32 "
        "{%0,%1,%2,%3},{%4,%5,%6,%7},{%8,%9},{%0,%1,%2,%3};"
        : "+f"(c[0]), "+f"(c[1]), "+f"(c[2]), "+f"(c[3])
        : "r"(a[0]), "r"(a[1]), "r"(a[2]), "r"(a[3]), "r"(b[0]), "r"(b[1]));
}

__device__ __forceinline__ float sigmoidf_(float x) { return 1.0f / (1.0f + expf(-x)); }

__device__ __forceinline__ void gbar() {
    __syncthreads();
    if (threadIdx.x == 0) {
        __threadfence();
        unsigned t = atomicAdd(&g_count, 1u) + 1u;
        unsigned epoch = (t + NBLK - 1u) / NBLK;
        if (t == epoch * NBLK) {
            atomicExch(&g_release, epoch);
        } else {
            while (*((volatile unsigned*)&g_release) < epoch) { }
        }
        __threadfence();
    }
    __syncthreads();
}

// ---------------- init: h state + barrier reset ----------------
__global__ void init_state_kernel(const float* __restrict__ h0) {
    int i = blockIdx.x * blockDim.x + threadIdx.x;
    if (i < B_ * P_) g_h[i] = h0[i];
    if (i == 0) { g_count = 0u; g_release = 0u; }
}

// ---------------- xg = x @ W_ih^T via TF32 mma (unchanged from R2) ----------------
#define XPAD 8
__global__ __launch_bounds__(256) void xg_mma_kernel(const float* __restrict__ X,
                                                     const float* __restrict__ Wih) {
    const int K = I_, N = G_;
    __shared__ unsigned As[16][128 + XPAD];
    __shared__ unsigned Bs[16][128 + XPAD];

    const int bm = blockIdx.y * 128;
    const int bn = blockIdx.x * 128;
    const int tid = threadIdx.x;
    const int lane = tid & 31, wid = tid >> 5;
    const int wm = (wid >> 2) * 64, wn = (wid & 3) * 32;
    const int g = lane >> 2, c = lane & 3;

    float acc[4][4][4];
#pragma unroll
    for (int i = 0; i < 4; i++)
#pragma unroll
        for (int j = 0; j < 4; j++)
#pragma unroll
            for (int r = 0; r < 4; r++) acc[i][j][r] = 0.0f;

    for (int k0 = 0; k0 < K; k0 += 16) {
#pragma unroll
        for (int it = 0; it < 2; it++) {
            int idx = it * 256 + tid;
            int row = idx >> 2;
            int kq = (idx & 3) * 4;
            float4 va = *(const float4*)(X + (size_t)(bm + row) * K + k0 + kq);
            As[kq + 0][row] = f2tf(va.x); As[kq + 1][row] = f2tf(va.y);
            As[kq + 2][row] = f2tf(va.z); As[kq + 3][row] = f2tf(va.w);
            float4 vb = *(const float4*)(Wih + (size_t)(bn + row) * K + k0 + kq);
            Bs[kq + 0][row] = f2tf(vb.x); Bs[kq + 1][row] = f2tf(vb.y);
            Bs[kq + 2][row] = f2tf(vb.z); Bs[kq + 3][row] = f2tf(vb.w);
        }
        __syncthreads();
#pragma unroll
        for (int kk = 0; kk < 16; kk += 8) {
            unsigned a[4][4], b[4][2];
#pragma unroll
            for (int i = 0; i < 4; i++) {
                int m = wm + i * 16;
                a[i][0] = As[kk + c][m + g];
                a[i][1] = As[kk + c][m + g + 8];
                a[i][2] = As[kk + c + 4][m + g];
                a[i][3] = As[kk + c + 4][m + g + 8];
            }
#pragma unroll
            for (int j = 0; j < 4; j++) {
                int n = wn + j * 8;
                b[j][0] = Bs[kk + c][n + g];
                b[j][1] = Bs[kk + 4 + c][n + g];
            }
#pragma unroll
            for (int i = 0; i < 4; i++)
#pragma unroll
                for (int j = 0; j < 4; j++) mma_tf32(acc[i][j], a[i], b[j]);
        }
        __syncthreads();
    }

#pragma unroll
    for (int i = 0; i < 4; i++) {
        int r0 = bm + wm + i * 16 + g;
#pragma unroll
        for (int j = 0; j < 4; j++) {
            int cc = bn + wn + j * 8 + c * 2;
            *(float2*)(g_xg + (size_t)r0 * N + cc)       = make_float2(acc[i][j][0], acc[i][j][1]);
            *(float2*)(g_xg + (size_t)(r0 + 8) * N + cc) = make_float2(acc[i][j][2], acc[i][j][3]);
        }
    }
}

// ---------------- persistent recurrence kernel ----------------
// 128 CTAs, 1/SM. Gates role (all CTAs): hc slice of 8 columns, all 128 batch rows.
// Proj role (CTAs 0..63): n-tile of 16 cols (bid&31), m-half of 64 rows (bid>>5).
__global__ __launch_bounds__(NTHR, 1) void lstm_persistent_kernel(
    const float* __restrict__ Whh, const float* __restrict__ Whr,
    const float* __restrict__ c0, float* __restrict__ out) {
    extern __shared__ unsigned sm[];
    unsigned* Whh_s = sm + OFF_WHH;
    unsigned* Whr_s = sm + OFF_WHR;
    unsigned* Asb   = sm + OFF_AS;
    float*    c_s   = (float*)(sm + OFF_C);

    const int bid = blockIdx.x;
    const int tid = threadIdx.x;
    const int lane = tid & 31, wid = tid >> 5;
    const int g = lane >> 2, c = lane & 3;
    const int hc0 = bid * 8;
    const bool pblk = (bid < PROJ_BLKS);
    const int bn = (bid & 31) * 16;
    const int bm = (bid >> 5) * 64;

    // ---- prologue: resident weights + c state ----
    for (int idx = tid; idx < 32 * 128; idx += NTHR) {         // Whh slice: 32 rows x 512
        int nl = idx >> 7, f4 = idx & 127;
        int grow = (nl >> 3) * H_ + hc0 + (nl & 7);
        float4 v = *(const float4*)(Whh + (size_t)grow * P_ + f4 * 4);
        unsigned* d = Whh_s + nl * WHH_S + f4 * 4;
        d[0] = f2tf(v.x); d[1] = f2tf(v.y); d[2] = f2tf(v.z); d[3] = f2tf(v.w);
    }
    if (pblk) {
        for (int idx = tid; idx < 16 * 256; idx += NTHR) {     // Whr tile: 16 rows x 1024
            int nl = idx >> 8, f4 = idx & 255;
            float4 v = *(const float4*)(Whr + (size_t)(bn + nl) * H_ + f4 * 4);
            unsigned* d = Whr_s + nl * WHR_S + f4 * 4;
            d[0] = f2tf(v.x); d[1] = f2tf(v.y); d[2] = f2tf(v.z); d[3] = f2tf(v.w);
        }
    }
    for (int idx = tid; idx < 1024; idx += NTHR) {             // c slice: [128 m][8 hc]
        int m = idx >> 3, hcl = idx & 7;
        c_s[idx] = c0[m * H_ + hc0 + hcl];
    }

    const size_t ysE = (size_t)T_ * B_ * P_;

    for (int t = 0; t < T_; t++) {
        // ================= GATES phase (all 128 CTAs) =================
        {
            float acc[4][4];
#pragma unroll
            for (int j = 0; j < 4; j++)
#pragma unroll
                for (int r = 0; r < 4; r++) acc[j][r] = 0.0f;

            const int mw = wid * 16;
            float4 pf[8];
#pragma unroll
            for (int it = 0; it < 8; it++) {
                int idx = it * NTHR + tid;
                int row = idx >> 4, f4 = idx & 15;
                pf[it] = __ldcg((const float4*)(g_h + (size_t)row * P_ + f4 * 4));
            }
            for (int kc = 0; kc < 8; kc++) {
                __syncthreads();
#pragma unroll
                for (int it = 0; it < 8; it++) {
                    int idx = it * NTHR + tid;
                    int row = idx >> 4, f4 = idx & 15;
                    uint4 sv;
                    sv.x = f2tf(pf[it].x); sv.y = f2tf(pf[it].y);
                    sv.z = f2tf(pf[it].z); sv.w = f2tf(pf[it].w);
                    *(uint4*)(Asb + row * AS_S + f4 * 4) = sv;
                }
                __syncthreads();
                if (kc < 7) {
#pragma unroll
                    for (int it = 0; it < 8; it++) {
                        int idx = it * NTHR + tid;
                        int row = idx >> 4, f4 = idx & 15;
                        pf[it] = __ldcg((const float4*)(g_h + (size_t)row * P_ + (kc + 1) * 64 + f4 * 4));
                    }
                }
                const int kb = kc * 64;
#pragma unroll
                for (int kk = 0; kk < 64; kk += 8) {
                    unsigned a[4];
                    a[0] = Asb[(mw + g) * AS_S + kk + c];
                    a[1] = Asb[(mw + g + 8) * AS_S + kk + c];
                    a[2] = Asb[(mw + g) * AS_S + kk + c + 4];
                    a[3] = Asb[(mw + g + 8) * AS_S + kk + c + 4];
#pragma unroll
                    for (int j = 0; j < 4; j++) {
                        unsigned b[2];
                        b[0] = Whh_s[(j * 8 + g) * WHH_S + kb + kk + c];
                        b[1] = Whh_s[(j * 8 + g) * WHH_S + kb + kk + 4 + c];
                        mma_tf32(acc[j], a, b);
                    }
                }
            }

            // fused epilogue: activations + cell update (c in smem) + hfull
            const float* xgp = g_xg + (size_t)t * B_ * G_;
#pragma unroll
            for (int rr = 0; rr < 2; rr++) {
                int m = mw + g + rr * 8;
                const float* xr = xgp + (size_t)m * G_;
#pragma unroll
                for (int cc = 0; cc < 2; cc++) {
                    int hcl = c * 2 + cc;
                    int hc = hc0 + hcl;
                    int ai = rr * 2 + cc;
                    float iv = acc[0][ai] + __ldg(xr + hc);
                    float fv = acc[1][ai] + __ldg(xr + H_ + hc);
                    float gv = acc[2][ai] + __ldg(xr + 2 * H_ + hc);
                    float ov = acc[3][ai] + __ldg(xr + 3 * H_ + hc);
                    iv = sigmoidf_(iv);
                    fv = sigmoidf_(fv);
                    gv = tanhf(gv);
                    ov = sigmoidf_(ov);
                    float cn = fv * c_s[m * 8 + hcl] + iv * gv;
                    c_s[m * 8 + hcl] = cn;
                    g_hfull[m * H_ + hc] = ov * tanhf(cn);
                }
            }
        }
        gbar();

        // ================= PROJ phase (CTAs 0..63) =================
        if (pblk) {
            float acc[4] = {0.0f, 0.0f, 0.0f, 0.0f};
            const int mtl = (wid & 3) * 16;      // local m-tile within 64 rows
            const int j = wid >> 2;              // n8 tile (0..1)

            float4 pf[4];
#pragma unroll
            for (int it = 0; it < 4; it++) {
                int idx = it * NTHR + tid;
                int row = idx >> 4, f4 = idx & 15;
                pf[it] = __ldcg((const float4*)(g_hfull + (size_t)(bm + row) * H_ + f4 * 4));
            }
            for (int kc = 0; kc < 16; kc++) {
                __syncthreads();
#pragma unroll
                for (int it = 0; it < 4; it++) {
                    int idx = it * NTHR + tid;
                    int row = idx >> 4, f4 = idx & 15;
                    uint4 sv;
                    sv.x = f2tf(pf[it].x); sv.y = f2tf(pf[it].y);
                    sv.z = f2tf(pf[it].z); sv.w = f2tf(pf[it].w);
                    *(uint4*)(Asb + row * AS_S + f4 * 4) = sv;
                }
                __syncthreads();
                if (kc < 15) {
#pragma unroll
                    for (int it = 0; it < 4; it++) {
                        int idx = it * NTHR + tid;
                        int row = idx >> 4, f4 = idx & 15;
                        pf[it] = __ldcg((const float4*)(g_hfull + (size_t)(bm + row) * H_ + (kc + 1) * 64 + f4 * 4));
                    }
                }
                const int kb = kc * 64;
#pragma unroll
                for (int kk = 0; kk < 64; kk += 8) {
                    unsigned a[4], b[2];
                    a[0] = Asb[(mtl + g) * AS_S + kk + c];
                    a[1] = Asb[(mtl + g + 8) * AS_S + kk + c];
                    a[2] = Asb[(mtl + g) * AS_S + kk + c + 4];
                    a[3] = Asb[(mtl + g + 8) * AS_S + kk + c + 4];
                    b[0] = Whr_s[(j * 8 + g) * WHR_S + kb + kk + c];
                    b[1] = Whr_s[(j * 8 + g) * WHR_S + kb + kk + 4 + c];
                    mma_tf32(acc, a, b);
                }
            }

            // write ys[t] and recurrent h
            float* yt = out + (size_t)t * B_ * P_;
            int m = bm + mtl + g;
            int n = bn + j * 8 + c * 2;
            *(float2*)(g_h + (size_t)m * P_ + n) = make_float2(acc[0], acc[1]);
            *(float2*)(yt + (size_t)m * P_ + n)  = make_float2(acc[0], acc[1]);
            *(float2*)(g_h + (size_t)(m + 8) * P_ + n) = make_float2(acc[2], acc[3]);
            *(float2*)(yt + (size_t)(m + 8) * P_ + n)  = make_float2(acc[2], acc[3]);
        }
        gbar();
    }

    // ---- final state outputs ----
    for (int i = bid * NTHR + tid; i < B_ * P_; i += NBLK * NTHR)
        out[ysE + i] = __ldcg(g_h + i);
    for (int idx = tid; idx < 1024; idx += NTHR) {
        int m = idx >> 3, hcl = idx & 7;
        out[ysE + B_ * P_ + (size_t)m * H_ + hc0 + hcl] = c_s[idx];
    }
}

// ---------------- launch ----------------
extern "C" void kernel_launch(void* const* d_in, const int* in_sizes, int n_in,
                              void* d_out, int out_size) {
    const float* x   = (const float*)d_in[0];   // [T,B,I]
    const float* h0  = (const float*)d_in[1];   // [1,B,P]
    const float* c0  = (const float*)d_in[2];   // [1,B,H]
    const float* Wih = (const float*)d_in[3];   // [4H,I]
    const float* Whh = (const float*)d_in[4];   // [4H,P]
    const float* Whr = (const float*)d_in[5];   // [P,H]
    float* out = (float*)d_out;                 // [ys | hT | cT]

    static int smem_set = 0;
    if (!smem_set) {
        cudaFuncSetAttribute(lstm_persistent_kernel,
                             cudaFuncAttributeMaxDynamicSharedMemorySize, SMEM_WORDS * 4);
        smem_set = 1;
    }

    init_state_kernel<<<(B_ * P_ + 255) / 256, 256>>>(h0);

    dim3 gx(G_ / 128, (T_ * B_) / 128);
    xg_mma_kernel<<<gx, 256>>>(x, Wih);

    lstm_persistent_kernel<<<NBLK, NTHR, SMEM_WORDS * 4>>>(Whh, Whr, c0, out);
}

// round 5
// speedup vs baseline: 5.1519x; 1.2361x over previous
#include <cuda_runtime.h>
#include <math.h>

#define T_ 256
#define B_ 128
#define I_ 1024
#define H_ 1024
#define P_ 512
#define G_ 4096  /* 4*H */

#define NBLK 128
#define NTHR 256
#define XPAD 8
#define HFT 32768  /* uint4 per timestep in g_hf: B*H/4 */

// ---------------- globals (no allocation) ----------------
__device__ float g_xg[(size_t)T_ * B_ * G_];     // [T*B, 4H] input gate contributions
__device__ float g_wc[(size_t)G_ * H_];          // W_comb = Whh @ Whr  [4096,1024] fp32
__device__ uint4 g_hf[(size_t)T_ * HFT];         // hfull, TF32 bits, mma-fragment layout per t
__device__ unsigned g_count;
__device__ unsigned g_release;

// ---------------- helpers ----------------
__device__ __forceinline__ unsigned f2tf(float x) {
    unsigned r;
    asm("cvt.rna.tf32.f32 %0, %1;" : "=r"(r) : "f"(x));
    return r;
}

__device__ __forceinline__ void mma_tf32(float* c, const unsigned* a, const unsigned* b) {
    asm volatile(
        "mma.sync.aligned.m16n8k8.row.col.f32.tf32.tf32.f32 "
        "{%0,%1,%2,%3},{%4,%5,%6,%7},{%8,%9},{%0,%1,%2,%3};"
        : "+f"(c[0]), "+f"(c[1]), "+f"(c[2]), "+f"(c[3])
        : "r"(a[0]), "r"(a[1]), "r"(a[2]), "r"(a[3]), "r"(b[0]), "r"(b[1]));
}

__device__ __forceinline__ float sigmoidf_(float x) { return 1.0f / (1.0f + expf(-x)); }

__device__ __forceinline__ unsigned smem_u32(const void* p) {
    return (unsigned)__cvta_generic_to_shared(p);
}

__device__ __forceinline__ void cp_async16(unsigned dst, const void* src) {
    asm volatile("cp.async.cg.shared.global [%0], [%1], 16;" :: "r"(dst), "l"(src));
}
__device__ __forceinline__ void cp_commit() { asm volatile("cp.async.commit_group;"); }
__device__ __forceinline__ void cp_wait0() { asm volatile("cp.async.wait_group 0;"); }

__device__ __forceinline__ void gbar() {
    __syncthreads();
    if (threadIdx.x == 0) {
        __threadfence();
        unsigned t = atomicAdd(&g_count, 1u) + 1u;
        unsigned epoch = (t + NBLK - 1u) / NBLK;
        if (t == epoch * NBLK) {
            atomicExch(&g_release, epoch);
        } else {
            while (*((volatile unsigned*)&g_release) < epoch) { }
        }
        __threadfence();
    }
    __syncthreads();
}

// ---------------- init: barrier reset ----------------
__global__ void init_kernel() {
    if (threadIdx.x == 0) { g_count = 0u; g_release = 0u; }
}

// ---------------- xg = x @ W_ih^T via TF32 mma ----------------
__global__ __launch_bounds__(256) void xg_mma_kernel(const float* __restrict__ X,
                                                     const float* __restrict__ Wih) {
    const int K = I_, N = G_;
    __shared__ unsigned As[16][128 + XPAD];
    __shared__ unsigned Bs[16][128 + XPAD];

    const int bm = blockIdx.y * 128;
    const int bn = blockIdx.x * 128;
    const int tid = threadIdx.x;
    const int lane = tid & 31, wid = tid >> 5;
    const int wm = (wid >> 2) * 64, wn = (wid & 3) * 32;
    const int g = lane >> 2, c = lane & 3;

    float acc[4][4][4];
#pragma unroll
    for (int i = 0; i < 4; i++)
#pragma unroll
        for (int j = 0; j < 4; j++)
#pragma unroll
            for (int r = 0; r < 4; r++) acc[i][j][r] = 0.0f;

    for (int k0 = 0; k0 < K; k0 += 16) {
#pragma unroll
        for (int it = 0; it < 2; it++) {
            int idx = it * 256 + tid;
            int row = idx >> 2;
            int kq = (idx & 3) * 4;
            float4 va = *(const float4*)(X + (size_t)(bm + row) * K + k0 + kq);
            As[kq + 0][row] = f2tf(va.x); As[kq + 1][row] = f2tf(va.y);
            As[kq + 2][row] = f2tf(va.z); As[kq + 3][row] = f2tf(va.w);
            float4 vb = *(const float4*)(Wih + (size_t)(bn + row) * K + k0 + kq);
            Bs[kq + 0][row] = f2tf(vb.x); Bs[kq + 1][row] = f2tf(vb.y);
            Bs[kq + 2][row] = f2tf(vb.z); Bs[kq + 3][row] = f2tf(vb.w);
        }
        __syncthreads();
#pragma unroll
        for (int kk = 0; kk < 16; kk += 8) {
            unsigned a[4][4], b[4][2];
#pragma unroll
            for (int i = 0; i < 4; i++) {
                int m = wm + i * 16;
                a[i][0] = As[kk + c][m + g];
                a[i][1] = As[kk + c][m + g + 8];
                a[i][2] = As[kk + c + 4][m + g];
                a[i][3] = As[kk + c + 4][m + g + 8];
            }
#pragma unroll
            for (int j = 0; j < 4; j++) {
                int n = wn + j * 8;
                b[j][0] = Bs[kk + c][n + g];
                b[j][1] = Bs[kk + 4 + c][n + g];
            }
#pragma unroll
            for (int i = 0; i < 4; i++)
#pragma unroll
                for (int j = 0; j < 4; j++) mma_tf32(acc[i][j], a[i], b[j]);
        }
        __syncthreads();
    }

#pragma unroll
    for (int i = 0; i < 4; i++) {
        int r0 = bm + wm + i * 16 + g;
#pragma unroll
        for (int j = 0; j < 4; j++) {
            int cc = bn + wn + j * 8 + c * 2;
            *(float2*)(g_xg + (size_t)r0 * N + cc)       = make_float2(acc[i][j][0], acc[i][j][1]);
            *(float2*)(g_xg + (size_t)(r0 + 8) * N + cc) = make_float2(acc[i][j][2], acc[i][j][3]);
        }
    }
}

// ---------------- fold h0 @ Whh^T into g_xg[t=0] ----------------
__global__ __launch_bounds__(256) void fold0_mma_kernel(const float* __restrict__ h0,
                                                        const float* __restrict__ Whh) {
    __shared__ unsigned As[16][128 + XPAD];
    __shared__ unsigned Bs[16][128 + XPAD];

    const int bn = blockIdx.x * 128;
    const int tid = threadIdx.x;
    const int lane = tid & 31, wid = tid >> 5;
    const int wm = (wid >> 2) * 64, wn = (wid & 3) * 32;
    const int g = lane >> 2, c = lane & 3;

    float acc[4][4][4];
#pragma unroll
    for (int i = 0; i < 4; i++)
#pragma unroll
        for (int j = 0; j < 4; j++)
#pragma unroll
            for (int r = 0; r < 4; r++) acc[i][j][r] = 0.0f;

    for (int k0 = 0; k0 < P_; k0 += 16) {
#pragma unroll
        for (int it = 0; it < 2; it++) {
            int idx = it * 256 + tid;
            int row = idx >> 2;
            int kq = (idx & 3) * 4;
            float4 va = *(const float4*)(h0 + (size_t)row * P_ + k0 + kq);
            As[kq + 0][row] = f2tf(va.x); As[kq + 1][row] = f2tf(va.y);
            As[kq + 2][row] = f2tf(va.z); As[kq + 3][row] = f2tf(va.w);
            float4 vb = *(const float4*)(Whh + (size_t)(bn + row) * P_ + k0 + kq);
            Bs[kq + 0][row] = f2tf(vb.x); Bs[kq + 1][row] = f2tf(vb.y);
            Bs[kq + 2][row] = f2tf(vb.z); Bs[kq + 3][row] = f2tf(vb.w);
        }
        __syncthreads();
#pragma unroll
        for (int kk = 0; kk < 16; kk += 8) {
            unsigned a[4][4], b[4][2];
#pragma unroll
            for (int i = 0; i < 4; i++) {
                int m = wm + i * 16;
                a[i][0] = As[kk + c][m + g];
                a[i][1] = As[kk + c][m + g + 8];
                a[i][2] = As[kk + c + 4][m + g];
                a[i][3] = As[kk + c + 4][m + g + 8];
            }
#pragma unroll
            for (int j = 0; j < 4; j++) {
                int n = wn + j * 8;
                b[j][0] = Bs[kk + c][n + g];
                b[j][1] = Bs[kk + 4 + c][n + g];
            }
#pragma unroll
            for (int i = 0; i < 4; i++)
#pragma unroll
                for (int j = 0; j < 4; j++) mma_tf32(acc[i][j], a[i], b[j]);
        }
        __syncthreads();
    }

#pragma unroll
    for (int i = 0; i < 4; i++) {
        int r0 = wm + i * 16 + g;
#pragma unroll
        for (int j = 0; j < 4; j++) {
            int cc = bn + wn + j * 8 + c * 2;
            float2* p0 = (float2*)(g_xg + (size_t)r0 * G_ + cc);
            float2* p1 = (float2*)(g_xg + (size_t)(r0 + 8) * G_ + cc);
            float2 o0 = *p0, o1 = *p1;
            *p0 = make_float2(o0.x + acc[i][j][0], o0.y + acc[i][j][1]);
            *p1 = make_float2(o1.x + acc[i][j][2], o1.y + acc[i][j][3]);
        }
    }
}

// ---------------- W_comb = Whh @ Whr  (3xTF32, ~fp32 accuracy) ----------------
__global__ __launch_bounds__(256) void wcomb_mma_kernel(const float* __restrict__ Whh,
                                                        const float* __restrict__ Whr) {
    __shared__ unsigned Ah[16][128 + XPAD], Al[16][128 + XPAD];
    __shared__ unsigned Bh[16][128 + XPAD], Bl[16][128 + XPAD];

    const int bm = blockIdx.y * 128;
    const int bn = blockIdx.x * 128;
    const int tid = threadIdx.x;
    const int lane = tid & 31, wid = tid >> 5;
    const int wm = (wid >> 2) * 64, wn = (wid & 3) * 32;
    const int g = lane >> 2, c = lane & 3;

    float acc[4][4][4];
#pragma unroll
    for (int i = 0; i < 4; i++)
#pragma unroll
        for (int j = 0; j < 4; j++)
#pragma unroll
            for (int r = 0; r < 4; r++) acc[i][j][r] = 0.0f;

    for (int k0 = 0; k0 < P_; k0 += 16) {
#pragma unroll
        for (int it = 0; it < 2; it++) {
            int idx = it * 256 + tid;
            {
                int row = idx >> 2;
                int kq = (idx & 3) * 4;
                float4 v = *(const float4*)(Whh + (size_t)(bm + row) * P_ + k0 + kq);
                float h0 = __uint_as_float(f2tf(v.x)), h1 = __uint_as_float(f2tf(v.y));
                float h2 = __uint_as_float(f2tf(v.z)), h3 = __uint_as_float(f2tf(v.w));
                Ah[kq + 0][row] = __float_as_uint(h0); Al[kq + 0][row] = f2tf(v.x - h0);
                Ah[kq + 1][row] = __float_as_uint(h1); Al[kq + 1][row] = f2tf(v.y - h1);
                Ah[kq + 2][row] = __float_as_uint(h2); Al[kq + 2][row] = f2tf(v.z - h2);
                Ah[kq + 3][row] = __float_as_uint(h3); Al[kq + 3][row] = f2tf(v.w - h3);
            }
            {
                int k = idx >> 5;
                int n4 = (idx & 31) * 4;
                float4 v = *(const float4*)(Whr + (size_t)(k0 + k) * H_ + bn + n4);
                float h0 = __uint_as_float(f2tf(v.x)), h1 = __uint_as_float(f2tf(v.y));
                float h2 = __uint_as_float(f2tf(v.z)), h3 = __uint_as_float(f2tf(v.w));
                Bh[k][n4 + 0] = __float_as_uint(h0); Bl[k][n4 + 0] = f2tf(v.x - h0);
                Bh[k][n4 + 1] = __float_as_uint(h1); Bl[k][n4 + 1] = f2tf(v.y - h1);
                Bh[k][n4 + 2] = __float_as_uint(h2); Bl[k][n4 + 2] = f2tf(v.z - h2);
                Bh[k][n4 + 3] = __float_as_uint(h3); Bl[k][n4 + 3] = f2tf(v.w - h3);
            }
        }
        __syncthreads();
#pragma unroll
        for (int kk = 0; kk < 16; kk += 8) {
            unsigned ah[4][4], al[4][4], bh[4][2], bl[4][2];
#pragma unroll
            for (int i = 0; i < 4; i++) {
                int m = wm + i * 16;
                ah[i][0] = Ah[kk + c][m + g];     al[i][0] = Al[kk + c][m + g];
                ah[i][1] = Ah[kk + c][m + g + 8]; al[i][1] = Al[kk + c][m + g + 8];
                ah[i][2] = Ah[kk + c + 4][m + g]; al[i][2] = Al[kk + c + 4][m + g];
                ah[i][3] = Ah[kk + c + 4][m + g + 8]; al[i][3] = Al[kk + c + 4][m + g + 8];
            }
#pragma unroll
            for (int j = 0; j < 4; j++) {
                int n = wn + j * 8;
                bh[j][0] = Bh[kk + c][n + g];     bl[j][0] = Bl[kk + c][n + g];
                bh[j][1] = Bh[kk + 4 + c][n + g]; bl[j][1] = Bl[kk + 4 + c][n + g];
            }
#pragma unroll
            for (int i = 0; i < 4; i++)
#pragma unroll
                for (int j = 0; j < 4; j++) {
                    mma_tf32(acc[i][j], al[i], bh[j]);
                    mma_tf32(acc[i][j], ah[i], bl[j]);
                    mma_tf32(acc[i][j], ah[i], bh[j]);
                }
        }
        __syncthreads();
    }

#pragma unroll
    for (int i = 0; i < 4; i++) {
        int r0 = bm + wm + i * 16 + g;
#pragma unroll
        for (int j = 0; j < 4; j++) {
            int cc = bn + wn + j * 8 + c * 2;
            *(float2*)(g_wc + (size_t)r0 * H_ + cc)       = make_float2(acc[i][j][0], acc[i][j][1]);
            *(float2*)(g_wc + (size_t)(r0 + 8) * H_ + cc) = make_float2(acc[i][j][2], acc[i][j][3]);
        }
    }
}

// ---------------- persistent recurrence: gates = xg[t] + hfull_{t-1} @ W_comb^T ----------------
__global__ __launch_bounds__(NTHR, 1) void lstm_seq_kernel(const float* __restrict__ c0,
                                                           float* __restrict__ out) {
    extern __shared__ __align__(16) unsigned smraw[];
    uint4* Wb   = (uint4*)smraw;           // [8192]  packed W_comb frags
    uint4* Abuf = Wb + 8192;               // [2][2048] hfull chunk frags (double buffer)
    float* bnc  = (float*)(Abuf + 4096);   // [1024]  epilogue bounce
    float* c_s  = bnc + 1024;              // [1024]  cell state [m][hcl]

    const int bid = blockIdx.x;
    const int tid = threadIdx.x;
    const int lane = tid & 31, wid = tid >> 5;
    const int g = lane >> 2, c = lane & 3;
    const int hc0 = bid * 8;

    // pack W_comb slice -> fragment-major smem (one-time)
    for (int idx = tid; idx < 8192; idx += NTHR) {
        int kt = idx >> 6, jh = (idx >> 5) & 1, ll = idx & 31;
        int gq = ll >> 2, cq = ll & 3;
        int col = kt * 8 + cq;
        const float* r0 = g_wc + (size_t)((jh * 2) * H_ + hc0 + gq) * H_ + col;
        const float* r1 = r0 + (size_t)H_ * H_;
        uint4 u;
        u.x = f2tf(r0[0]); u.y = f2tf(r0[4]);
        u.z = f2tf(r1[0]); u.w = f2tf(r1[4]);
        Wb[idx] = u;
    }
    for (int idx = tid; idx < 1024; idx += NTHR)
        c_s[idx] = c0[(idx >> 3) * H_ + hc0 + (idx & 7)];
    __syncthreads();

    const unsigned sA = smem_u32(Abuf);

    for (int t = 0; t < T_; t++) {
        float acc[4][4];
#pragma unroll
        for (int j = 0; j < 4; j++)
#pragma unroll
            for (int r = 0; r < 4; r++) acc[j][r] = 0.0f;

        if (t > 0) {
            const uint4* src = g_hf + (size_t)(t - 1) * HFT;
#pragma unroll
            for (int it = 0; it < 8; it++) {
                int idx = it * NTHR + tid;
                cp_async16(sA + idx * 16, src + idx);
            }
            cp_commit();
            for (int ch = 0; ch < 16; ch++) {
                cp_wait0();
                __syncthreads();
                if (ch < 15) {
                    int bsel = (ch + 1) & 1;
#pragma unroll
                    for (int it = 0; it < 8; it++) {
                        int idx = it * NTHR + tid;
                        cp_async16(sA + (bsel * 2048 + idx) * 16, src + (ch + 1) * 2048 + idx);
                    }
                    cp_commit();
                }
                const uint4* Ab = Abuf + (ch & 1) * 2048;
#pragma unroll
                for (int k8 = 0; k8 < 8; k8++) {
                    int kt = ch * 8 + k8;
                    uint4 av = Ab[(k8 * 8 + wid) * 32 + lane];
                    uint4 w0 = Wb[(kt * 2 + 0) * 32 + lane];
                    uint4 w1 = Wb[(kt * 2 + 1) * 32 + lane];
                    unsigned a4[4] = {av.x, av.y, av.z, av.w};
                    unsigned b0[2] = {w0.x, w0.y}, b1[2] = {w0.z, w0.w};
                    unsigned b2[2] = {w1.x, w1.y}, b3[2] = {w1.z, w1.w};
                    mma_tf32(acc[0], a4, b0);
                    mma_tf32(acc[1], a4, b1);
                    mma_tf32(acc[2], a4, b2);
                    mma_tf32(acc[3], a4, b3);
                }
            }
        }

        // epilogue: activations + cell update + fragment-layout hfull write
        const float* xgp = g_xg + (size_t)t * B_ * G_;
#pragma unroll
        for (int gh = 0; gh < 2; gh++) {
            int m = wid * 16 + g + gh * 8;
            const float* xr = xgp + (size_t)m * G_ + hc0 + c * 2;
            float2 xi = __ldg((const float2*)(xr));
            float2 xf = __ldg((const float2*)(xr + H_));
            float2 xv = __ldg((const float2*)(xr + 2 * H_));
            float2 xo = __ldg((const float2*)(xr + 3 * H_));
#pragma unroll
            for (int cc = 0; cc < 2; cc++) {
                int r = gh * 2 + cc;
                float iv = sigmoidf_(acc[0][r] + (cc ? xi.y : xi.x));
                float fv = sigmoidf_(acc[1][r] + (cc ? xf.y : xf.x));
                float gv = tanhf(acc[2][r] + (cc ? xv.y : xv.x));
                float ov = sigmoidf_(acc[3][r] + (cc ? xo.y : xo.x));
                int ci = m * 8 + c * 2 + cc;
                float cn = fv * c_s[ci] + iv * gv;
                c_s[ci] = cn;
                bnc[wid * 128 + (g + gh * 8) * 8 + c * 2 + cc] = ov * tanhf(cn);
            }
        }
        __syncwarp();
        {
            const float* bw = bnc + wid * 128;
            uint4 u;
            u.x = f2tf(bw[g * 8 + c]);
            u.y = f2tf(bw[(g + 8) * 8 + c]);
            u.z = f2tf(bw[g * 8 + c + 4]);
            u.w = f2tf(bw[(g + 8) * 8 + c + 4]);
            g_hf[(size_t)t * HFT + (bid * 8 + wid) * 32 + lane] = u;
        }
        gbar();
    }

    // cT output
    const size_t ysE = (size_t)T_ * B_ * P_;
    for (int idx = tid; idx < 1024; idx += NTHR)
        out[ysE + B_ * P_ + (size_t)(idx >> 3) * H_ + hc0 + (idx & 7)] = c_s[idx];
}

// ---------------- Y = HFULL @ Whr^T : all ys at once ----------------
__global__ __launch_bounds__(256) void y_mma_kernel(const float* __restrict__ Whr,
                                                    float* __restrict__ out) {
    __shared__ uint4 Asf[512];
    __shared__ unsigned Bs[16][128 + XPAD];

    const int tt = blockIdx.y;
    const int bn = blockIdx.x * 128;
    const int tid = threadIdx.x;
    const int lane = tid & 31, wid = tid >> 5;
    const int wm = (wid >> 2) * 64, wn = (wid & 3) * 32;
    const int g = lane >> 2, c = lane & 3;

    float acc[4][4][4];
#pragma unroll
    for (int i = 0; i < 4; i++)
#pragma unroll
        for (int j = 0; j < 4; j++)
#pragma unroll
            for (int r = 0; r < 4; r++) acc[i][j][r] = 0.0f;

    const uint4* Af = g_hf + (size_t)tt * HFT;

    for (int k0 = 0; k0 < H_; k0 += 16) {
        int ktb = k0 >> 3;
#pragma unroll
        for (int it = 0; it < 2; it++) {
            int idx = it * 256 + tid;
            Asf[idx] = Af[ktb * 256 + idx];
            int row = idx >> 2;
            int kq = (idx & 3) * 4;
            float4 v = *(const float4*)(Whr + (size_t)(bn + row) * H_ + k0 + kq);
            Bs[kq + 0][row] = f2tf(v.x); Bs[kq + 1][row] = f2tf(v.y);
            Bs[kq + 2][row] = f2tf(v.z); Bs[kq + 3][row] = f2tf(v.w);
        }
        __syncthreads();
#pragma unroll
        for (int k2 = 0; k2 < 2; k2++) {
            unsigned b[4][2];
#pragma unroll
            for (int j = 0; j < 4; j++) {
                int n = wn + j * 8;
                b[j][0] = Bs[k2 * 8 + c][n + g];
                b[j][1] = Bs[k2 * 8 + 4 + c][n + g];
            }
#pragma unroll
            for (int i = 0; i < 4; i++) {
                int mi = (wm >> 4) + i;
                uint4 av = Asf[(k2 * 8 + mi) * 32 + lane];
                unsigned a4[4] = {av.x, av.y, av.z, av.w};
#pragma unroll
                for (int j = 0; j < 4; j++) mma_tf32(acc[i][j], a4, b[j]);
            }
        }
        __syncthreads();
    }

#pragma unroll
    for (int i = 0; i < 4; i++) {
        int r0 = tt * 128 + wm + i * 16 + g;
#pragma unroll
        for (int j = 0; j < 4; j++) {
            int cc = bn + wn + j * 8 + c * 2;
            *(float2*)(out + (size_t)r0 * P_ + cc)       = make_float2(acc[i][j][0], acc[i][j][1]);
            *(float2*)(out + (size_t)(r0 + 8) * P_ + cc) = make_float2(acc[i][j][2], acc[i][j][3]);
        }
    }
}

// ---------------- hT = ys[T-1] ----------------
__global__ void tail_kernel(float* __restrict__ out) {
    int i = blockIdx.x * blockDim.x + threadIdx.x;
    if (i < B_ * P_)
        out[(size_t)T_ * B_ * P_ + i] = out[(size_t)(T_ * B_ - B_) * P_ + i];
}

// ---------------- launch ----------------
extern "C" void kernel_launch(void* const* d_in, const int* in_sizes, int n_in,
                              void* d_out, int out_size) {
    const float* x   = (const float*)d_in[0];   // [T,B,I]
    const float* h0  = (const float*)d_in[1];   // [1,B,P]
    const float* c0  = (const float*)d_in[2];   // [1,B,H]
    const float* Wih = (const float*)d_in[3];   // [4H,I]
    const float* Whh = (const float*)d_in[4];   // [4H,P]
    const float* Whr = (const float*)d_in[5];   // [P,H]
    float* out = (float*)d_out;                 // [ys | hT | cT]

    static int smem_set = 0;
    if (!smem_set) {
        cudaFuncSetAttribute(lstm_seq_kernel,
                             cudaFuncAttributeMaxDynamicSharedMemorySize, 204800);
        smem_set = 1;
    }

    init_kernel<<<1, 32>>>();

    dim3 gx(G_ / 128, (T_ * B_) / 128);
    xg_mma_kernel<<<gx, 256>>>(x, Wih);
    fold0_mma_kernel<<<G_ / 128, 256>>>(h0, Whh);

    dim3 gw(H_ / 128, G_ / 128);
    wcomb_mma_kernel<<<gw, 256>>>(Whh, Whr);

    lstm_seq_kernel<<<NBLK, NTHR, 204800>>>(c0, out);

    dim3 gy(P_ / 128, T_);
    y_mma_kernel<<<gy, 256>>>(Whr, out);
    tail_kernel<<<(B_ * P_ + 255) / 256, 256>>>(out);
}

// round 6
// speedup vs baseline: 5.5857x; 1.0842x over previous
#include <cuda_runtime.h>
#include <math.h>

#define T_ 256
#define B_ 128
#define I_ 1024
#define H_ 1024
#define P_ 512
#define G_ 4096  /* 4*H */

#define NBLK 128
#define NTHR 256
#define XPAD 8
#define HFT 32768  /* uint4 per timestep in g_hf: B*H/4 */

// ---------------- globals (no allocation) ----------------
__device__ float g_xg[(size_t)T_ * B_ * G_];     // [T*B, 4H] input gate contributions
__device__ float g_wc[(size_t)G_ * H_];          // W_comb = Whh @ Whr  [4096,1024] fp32
__device__ uint4 g_hf[(size_t)T_ * HFT];         // hfull, TF32 bits, mma-fragment layout per t
__device__ int g_flags[NBLK * 8];                // per-CTA step flags (32B stride)

// ---------------- helpers ----------------
__device__ __forceinline__ unsigned f2tf(float x) {
    unsigned r;
    asm("cvt.rna.tf32.f32 %0, %1;" : "=r"(r) : "f"(x));
    return r;
}

__device__ __forceinline__ void mma_tf32(float* c, const unsigned* a, const unsigned* b) {
    asm volatile(
        "mma.sync.aligned.m16n8k8.row.col.f32.tf32.tf32.f32 "
        "{%0,%1,%2,%3},{%4,%5,%6,%7},{%8,%9},{%0,%1,%2,%3};"
        : "+f"(c[0]), "+f"(c[1]), "+f"(c[2]), "+f"(c[3])
        : "r"(a[0]), "r"(a[1]), "r"(a[2]), "r"(a[3]), "r"(b[0]), "r"(b[1]));
}

__device__ __forceinline__ float sigmoidf_(float x) { return 1.0f / (1.0f + expf(-x)); }

__device__ __forceinline__ unsigned smem_u32(const void* p) {
    return (unsigned)__cvta_generic_to_shared(p);
}

__device__ __forceinline__ void cp_async16(unsigned dst, const void* src) {
    asm volatile("cp.async.cg.shared.global [%0], [%1], 16;" :: "r"(dst), "l"(src));
}
__device__ __forceinline__ void cp_commit() { asm volatile("cp.async.commit_group;"); }
__device__ __forceinline__ void cp_wait0() { asm volatile("cp.async.wait_group 0;"); }

// ---------------- init: flag reset ----------------
__global__ void init_kernel() {
    int i = blockIdx.x * blockDim.x + threadIdx.x;
    if (i < NBLK * 8) g_flags[i] = 0;
}

// ---------------- xg = x @ W_ih^T via TF32 mma ----------------
__global__ __launch_bounds__(256) void xg_mma_kernel(const float* __restrict__ X,
                                                     const float* __restrict__ Wih) {
    const int K = I_, N = G_;
    __shared__ unsigned As[16][128 + XPAD];
    __shared__ unsigned Bs[16][128 + XPAD];

    const int bm = blockIdx.y * 128;
    const int bn = blockIdx.x * 128;
    const int tid = threadIdx.x;
    const int lane = tid & 31, wid = tid >> 5;
    const int wm = (wid >> 2) * 64, wn = (wid & 3) * 32;
    const int g = lane >> 2, c = lane & 3;

    float acc[4][4][4];
#pragma unroll
    for (int i = 0; i < 4; i++)
#pragma unroll
        for (int j = 0; j < 4; j++)
#pragma unroll
            for (int r = 0; r < 4; r++) acc[i][j][r] = 0.0f;

    for (int k0 = 0; k0 < K; k0 += 16) {
#pragma unroll
        for (int it = 0; it < 2; it++) {
            int idx = it * 256 + tid;
            int row = idx >> 2;
            int kq = (idx & 3) * 4;
            float4 va = *(const float4*)(X + (size_t)(bm + row) * K + k0 + kq);
            As[kq + 0][row] = f2tf(va.x); As[kq + 1][row] = f2tf(va.y);
            As[kq + 2][row] = f2tf(va.z); As[kq + 3][row] = f2tf(va.w);
            float4 vb = *(const float4*)(Wih + (size_t)(bn + row) * K + k0 + kq);
            Bs[kq + 0][row] = f2tf(vb.x); Bs[kq + 1][row] = f2tf(vb.y);
            Bs[kq + 2][row] = f2tf(vb.z); Bs[kq + 3][row] = f2tf(vb.w);
        }
        __syncthreads();
#pragma unroll
        for (int kk = 0; kk < 16; kk += 8) {
            unsigned a[4][4], b[4][2];
#pragma unroll
            for (int i = 0; i < 4; i++) {
                int m = wm + i * 16;
                a[i][0] = As[kk + c][m + g];
                a[i][1] = As[kk + c][m + g + 8];
                a[i][2] = As[kk + c + 4][m + g];
                a[i][3] = As[kk + c + 4][m + g + 8];
            }
#pragma unroll
            for (int j = 0; j < 4; j++) {
                int n = wn + j * 8;
                b[j][0] = Bs[kk + c][n + g];
                b[j][1] = Bs[kk + 4 + c][n + g];
            }
#pragma unroll
            for (int i = 0; i < 4; i++)
#pragma unroll
                for (int j = 0; j < 4; j++) mma_tf32(acc[i][j], a[i], b[j]);
        }
        __syncthreads();
    }

#pragma unroll
    for (int i = 0; i < 4; i++) {
        int r0 = bm + wm + i * 16 + g;
#pragma unroll
        for (int j = 0; j < 4; j++) {
            int cc = bn + wn + j * 8 + c * 2;
            *(float2*)(g_xg + (size_t)r0 * N + cc)       = make_float2(acc[i][j][0], acc[i][j][1]);
            *(float2*)(g_xg + (size_t)(r0 + 8) * N + cc) = make_float2(acc[i][j][2], acc[i][j][3]);
        }
    }
}

// ---------------- fold h0 @ Whh^T into g_xg[t=0] ----------------
__global__ __launch_bounds__(256) void fold0_mma_kernel(const float* __restrict__ h0,
                                                        const float* __restrict__ Whh) {
    __shared__ unsigned As[16][128 + XPAD];
    __shared__ unsigned Bs[16][128 + XPAD];

    const int bn = blockIdx.x * 128;
    const int tid = threadIdx.x;
    const int lane = tid & 31, wid = tid >> 5;
    const int wm = (wid >> 2) * 64, wn = (wid & 3) * 32;
    const int g = lane >> 2, c = lane & 3;

    float acc[4][4][4];
#pragma unroll
    for (int i = 0; i < 4; i++)
#pragma unroll
        for (int j = 0; j < 4; j++)
#pragma unroll
            for (int r = 0; r < 4; r++) acc[i][j][r] = 0.0f;

    for (int k0 = 0; k0 < P_; k0 += 16) {
#pragma unroll
        for (int it = 0; it < 2; it++) {
            int idx = it * 256 + tid;
            int row = idx >> 2;
            int kq = (idx & 3) * 4;
            float4 va = *(const float4*)(h0 + (size_t)row * P_ + k0 + kq);
            As[kq + 0][row] = f2tf(va.x); As[kq + 1][row] = f2tf(va.y);
            As[kq + 2][row] = f2tf(va.z); As[kq + 3][row] = f2tf(va.w);
            float4 vb = *(const float4*)(Whh + (size_t)(bn + row) * P_ + k0 + kq);
            Bs[kq + 0][row] = f2tf(vb.x); Bs[kq + 1][row] = f2tf(vb.y);
            Bs[kq + 2][row] = f2tf(vb.z); Bs[kq + 3][row] = f2tf(vb.w);
        }
        __syncthreads();
#pragma unroll
        for (int kk = 0; kk < 16; kk += 8) {
            unsigned a[4][4], b[4][2];
#pragma unroll
            for (int i = 0; i < 4; i++) {
                int m = wm + i * 16;
                a[i][0] = As[kk + c][m + g];
                a[i][1] = As[kk + c][m + g + 8];
                a[i][2] = As[kk + c + 4][m + g];
                a[i][3] = As[kk + c + 4][m + g + 8];
            }
#pragma unroll
            for (int j = 0; j < 4; j++) {
                int n = wn + j * 8;
                b[j][0] = Bs[kk + c][n + g];
                b[j][1] = Bs[kk + 4 + c][n + g];
            }
#pragma unroll
            for (int i = 0; i < 4; i++)
#pragma unroll
                for (int j = 0; j < 4; j++) mma_tf32(acc[i][j], a[i], b[j]);
        }
        __syncthreads();
    }

#pragma unroll
    for (int i = 0; i < 4; i++) {
        int r0 = wm + i * 16 + g;
#pragma unroll
        for (int j = 0; j < 4; j++) {
            int cc = bn + wn + j * 8 + c * 2;
            float2* p0 = (float2*)(g_xg + (size_t)r0 * G_ + cc);
            float2* p1 = (float2*)(g_xg + (size_t)(r0 + 8) * G_ + cc);
            float2 o0 = *p0, o1 = *p1;
            *p0 = make_float2(o0.x + acc[i][j][0], o0.y + acc[i][j][1]);
            *p1 = make_float2(o1.x + acc[i][j][2], o1.y + acc[i][j][3]);
        }
    }
}

// ---------------- W_comb = Whh @ Whr  (3xTF32, ~fp32 accuracy) ----------------
__global__ __launch_bounds__(256) void wcomb_mma_kernel(const float* __restrict__ Whh,
                                                        const float* __restrict__ Whr) {
    __shared__ unsigned Ah[16][128 + XPAD], Al[16][128 + XPAD];
    __shared__ unsigned Bh[16][128 + XPAD], Bl[16][128 + XPAD];

    const int bm = blockIdx.y * 128;
    const int bn = blockIdx.x * 128;
    const int tid = threadIdx.x;
    const int lane = tid & 31, wid = tid >> 5;
    const int wm = (wid >> 2) * 64, wn = (wid & 3) * 32;
    const int g = lane >> 2, c = lane & 3;

    float acc[4][4][4];
#pragma unroll
    for (int i = 0; i < 4; i++)
#pragma unroll
        for (int j = 0; j < 4; j++)
#pragma unroll
            for (int r = 0; r < 4; r++) acc[i][j][r] = 0.0f;

    for (int k0 = 0; k0 < P_; k0 += 16) {
#pragma unroll
        for (int it = 0; it < 2; it++) {
            int idx = it * 256 + tid;
            {
                int row = idx >> 2;
                int kq = (idx & 3) * 4;
                float4 v = *(const float4*)(Whh + (size_t)(bm + row) * P_ + k0 + kq);
                float h0 = __uint_as_float(f2tf(v.x)), h1 = __uint_as_float(f2tf(v.y));
                float h2 = __uint_as_float(f2tf(v.z)), h3 = __uint_as_float(f2tf(v.w));
                Ah[kq + 0][row] = __float_as_uint(h0); Al[kq + 0][row] = f2tf(v.x - h0);
                Ah[kq + 1][row] = __float_as_uint(h1); Al[kq + 1][row] = f2tf(v.y - h1);
                Ah[kq + 2][row] = __float_as_uint(h2); Al[kq + 2][row] = f2tf(v.z - h2);
                Ah[kq + 3][row] = __float_as_uint(h3); Al[kq + 3][row] = f2tf(v.w - h3);
            }
            {
                int k = idx >> 5;
                int n4 = (idx & 31) * 4;
                float4 v = *(const float4*)(Whr + (size_t)(k0 + k) * H_ + bn + n4);
                float h0 = __uint_as_float(f2tf(v.x)), h1 = __uint_as_float(f2tf(v.y));
                float h2 = __uint_as_float(f2tf(v.z)), h3 = __uint_as_float(f2tf(v.w));
                Bh[k][n4 + 0] = __float_as_uint(h0); Bl[k][n4 + 0] = f2tf(v.x - h0);
                Bh[k][n4 + 1] = __float_as_uint(h1); Bl[k][n4 + 1] = f2tf(v.y - h1);
                Bh[k][n4 + 2] = __float_as_uint(h2); Bl[k][n4 + 2] = f2tf(v.z - h2);
                Bh[k][n4 + 3] = __float_as_uint(h3); Bl[k][n4 + 3] = f2tf(v.w - h3);
            }
        }
        __syncthreads();
#pragma unroll
        for (int kk = 0; kk < 16; kk += 8) {
            unsigned ah[4][4], al[4][4], bh[4][2], bl[4][2];
#pragma unroll
            for (int i = 0; i < 4; i++) {
                int m = wm + i * 16;
                ah[i][0] = Ah[kk + c][m + g];     al[i][0] = Al[kk + c][m + g];
                ah[i][1] = Ah[kk + c][m + g + 8]; al[i][1] = Al[kk + c][m + g + 8];
                ah[i][2] = Ah[kk + c + 4][m + g]; al[i][2] = Al[kk + c + 4][m + g];
                ah[i][3] = Ah[kk + c + 4][m + g + 8]; al[i][3] = Al[kk + c + 4][m + g + 8];
            }
#pragma unroll
            for (int j = 0; j < 4; j++) {
                int n = wn + j * 8;
                bh[j][0] = Bh[kk + c][n + g];     bl[j][0] = Bl[kk + c][n + g];
                bh[j][1] = Bh[kk + 4 + c][n + g]; bl[j][1] = Bl[kk + 4 + c][n + g];
            }
#pragma unroll
            for (int i = 0; i < 4; i++)
#pragma unroll
                for (int j = 0; j < 4; j++) {
                    mma_tf32(acc[i][j], al[i], bh[j]);
                    mma_tf32(acc[i][j], ah[i], bl[j]);
                    mma_tf32(acc[i][j], ah[i], bh[j]);
                }
        }
        __syncthreads();
    }

#pragma unroll
    for (int i = 0; i < 4; i++) {
        int r0 = bm + wm + i * 16 + g;
#pragma unroll
        for (int j = 0; j < 4; j++) {
            int cc = bn + wn + j * 8 + c * 2;
            *(float2*)(g_wc + (size_t)r0 * H_ + cc)       = make_float2(acc[i][j][0], acc[i][j][1]);
            *(float2*)(g_wc + (size_t)(r0 + 8) * H_ + cc) = make_float2(acc[i][j][2], acc[i][j][3]);
        }
    }
}

// ---------------- persistent recurrence: gates = xg[t] + hfull_{t-1} @ W_comb^T ----------------
// 128 CTAs x 256 thr. CTA owns 8 h-cols (kt = bid). Warps 0-3 compute (m=2,n=4 tiles);
// warps 4-7 stage hfull chunks via cp.async. Flag-array global barrier, 1 per step.
__global__ __launch_bounds__(NTHR, 1) void lstm_seq_kernel(const float* __restrict__ c0,
                                                           float* __restrict__ out) {
    extern __shared__ __align__(16) unsigned smraw[];
    uint4* Wb   = (uint4*)smraw;           // [8192]  packed W_comb frags (128 KB)
    uint4* Abuf = Wb + 8192;               // [2][2048] hfull chunk frags (64 KB)
    float* bnc  = (float*)(Abuf + 4096);   // [1024]  epilogue bounce (8 tiles x 128)
    float* c_s  = bnc + 1024;              // [1024]  cell state [m][hcl]

    const int bid = blockIdx.x;
    const int tid = threadIdx.x;
    const int lane = tid & 31, wid = tid >> 5;
    const int g = lane >> 2, c = lane & 3;
    const int hc0 = bid * 8;
    const bool isMma = (wid < 4);

    // pack W_comb slice -> fragment-major smem (one-time)
    for (int idx = tid; idx < 8192; idx += NTHR) {
        int kt = idx >> 6, jh = (idx >> 5) & 1, ll = idx & 31;
        int gq = ll >> 2, cq = ll & 3;
        int col = kt * 8 + cq;
        const float* r0 = g_wc + (size_t)((jh * 2) * H_ + hc0 + gq) * H_ + col;
        const float* r1 = r0 + (size_t)H_ * H_;
        uint4 u;
        u.x = f2tf(r0[0]); u.y = f2tf(r0[4]);
        u.z = f2tf(r1[0]); u.w = f2tf(r1[4]);
        Wb[idx] = u;
    }
    for (int idx = tid; idx < 1024; idx += NTHR)
        c_s[idx] = c0[(idx >> 3) * H_ + hc0 + (idx & 7)];
    __syncthreads();

    const unsigned sA = smem_u32(Abuf);
    volatile int* flags = (volatile int*)g_flags;

    for (int t = 0; t < T_; t++) {
        float acc[2][4][4];
#pragma unroll
        for (int mi = 0; mi < 2; mi++)
#pragma unroll
            for (int j = 0; j < 4; j++)
#pragma unroll
                for (int r = 0; r < 4; r++) acc[mi][j][r] = 0.0f;

        // prefetch xg into regs (overlaps with the poll + pipeline)
        float xgv[2][2][4][2];
        if (isMma) {
            const float* xgp = g_xg + (size_t)t * B_ * G_;
#pragma unroll
            for (int mi = 0; mi < 2; mi++)
#pragma unroll
                for (int gh = 0; gh < 2; gh++) {
                    int m = (2 * wid + mi) * 16 + g + gh * 8;
                    const float* xr = xgp + (size_t)m * G_ + hc0 + c * 2;
#pragma unroll
                    for (int j = 0; j < 4; j++) {
                        float2 v = __ldg((const float2*)(xr + j * H_));
                        xgv[mi][gh][j][0] = v.x;
                        xgv[mi][gh][j][1] = v.y;
                    }
                }
        }

        if (t > 0) {
            // wait for all CTAs to publish step t-1
            for (;;) {
                int ok = 1;
                if (tid < NBLK) ok = (flags[tid * 8] >= t);
                if (__syncthreads_and(ok)) break;
            }
            __threadfence();

            const uint4* src = g_hf + (size_t)(t - 1) * HFT;
            if (!isMma) {
                int tid2 = tid & 127;
#pragma unroll
                for (int it = 0; it < 16; it++) {
                    int idx = it * 128 + tid2;
                    cp_async16(sA + idx * 16, src + idx);
                }
                cp_commit();
            }
            for (int ch = 0; ch < 16; ch++) {
                cp_wait0();
                __syncthreads();
                if (!isMma && ch < 15) {
                    int tid2 = tid & 127;
                    int boff = ((ch + 1) & 1) * 2048;
#pragma unroll
                    for (int it = 0; it < 16; it++) {
                        int idx = it * 128 + tid2;
                        cp_async16(sA + (boff + idx) * 16, src + (ch + 1) * 2048 + idx);
                    }
                    cp_commit();
                }
                if (isMma) {
                    const uint4* Ab = Abuf + (ch & 1) * 2048;
#pragma unroll
                    for (int k8 = 0; k8 < 8; k8++) {
                        int kt = ch * 8 + k8;
                        uint4 a0 = Ab[(k8 * 8 + 2 * wid) * 32 + lane];
                        uint4 a1 = Ab[(k8 * 8 + 2 * wid + 1) * 32 + lane];
                        uint4 w0 = Wb[(kt * 2 + 0) * 32 + lane];
                        uint4 w1 = Wb[(kt * 2 + 1) * 32 + lane];
                        unsigned A0[4] = {a0.x, a0.y, a0.z, a0.w};
                        unsigned A1[4] = {a1.x, a1.y, a1.z, a1.w};
                        unsigned b0[2] = {w0.x, w0.y}, b1[2] = {w0.z, w0.w};
                        unsigned b2[2] = {w1.x, w1.y}, b3[2] = {w1.z, w1.w};
                        mma_tf32(acc[0][0], A0, b0);
                        mma_tf32(acc[0][1], A0, b1);
                        mma_tf32(acc[0][2], A0, b2);
                        mma_tf32(acc[0][3], A0, b3);
                        mma_tf32(acc[1][0], A1, b0);
                        mma_tf32(acc[1][1], A1, b1);
                        mma_tf32(acc[1][2], A1, b2);
                        mma_tf32(acc[1][3], A1, b3);
                    }
                }
            }
        }

        // epilogue: activations + cell update + fragment-layout hfull store (mma warps)
        if (isMma) {
#pragma unroll
            for (int mi = 0; mi < 2; mi++) {
                int mt = 2 * wid + mi;
#pragma unroll
                for (int gh = 0; gh < 2; gh++) {
                    int m = mt * 16 + g + gh * 8;
#pragma unroll
                    for (int cc = 0; cc < 2; cc++) {
                        int r = gh * 2 + cc;
                        float iv = sigmoidf_(acc[mi][0][r] + xgv[mi][gh][0][cc]);
                        float fv = sigmoidf_(acc[mi][1][r] + xgv[mi][gh][1][cc]);
                        float gv = tanhf(acc[mi][2][r] + xgv[mi][gh][2][cc]);
                        float ov = sigmoidf_(acc[mi][3][r] + xgv[mi][gh][3][cc]);
                        int ci = m * 8 + c * 2 + cc;
                        float cn = fv * c_s[ci] + iv * gv;
                        c_s[ci] = cn;
                        bnc[mt * 128 + (g + gh * 8) * 8 + c * 2 + cc] = ov * tanhf(cn);
                    }
                }
            }
            __syncwarp();
#pragma unroll
            for (int mi = 0; mi < 2; mi++) {
                int mt = 2 * wid + mi;
                const float* bt = bnc + mt * 128;
                uint4 u;
                u.x = f2tf(bt[g * 8 + c]);
                u.y = f2tf(bt[(g + 8) * 8 + c]);
                u.z = f2tf(bt[g * 8 + c + 4]);
                u.w = f2tf(bt[(g + 8) * 8 + c + 4]);
                g_hf[(size_t)t * HFT + ((size_t)bid * 8 + mt) * 32 + lane] = u;
            }
        }

        // publish step t
        __threadfence();
        __syncthreads();
        if (tid == 0) flags[bid * 8] = t + 1;
    }

    // cT output
    const size_t ysE = (size_t)T_ * B_ * P_;
    for (int idx = tid; idx < 1024; idx += NTHR)
        out[ysE + B_ * P_ + (size_t)(idx >> 3) * H_ + hc0 + (idx & 7)] = c_s[idx];
}

// ---------------- Y = HFULL @ Whr^T : all ys at once ----------------
__global__ __launch_bounds__(256) void y_mma_kernel(const float* __restrict__ Whr,
                                                    float* __restrict__ out) {
    __shared__ uint4 Asf[512];
    __shared__ unsigned Bs[16][128 + XPAD];

    const int tt = blockIdx.y;
    const int bn = blockIdx.x * 128;
    const int tid = threadIdx.x;
    const int lane = tid & 31, wid = tid >> 5;
    const int wm = (wid >> 2) * 64, wn = (wid & 3) * 32;
    const int g = lane >> 2, c = lane & 3;

    float acc[4][4][4];
#pragma unroll
    for (int i = 0; i < 4; i++)
#pragma unroll
        for (int j = 0; j < 4; j++)
#pragma unroll
            for (int r = 0; r < 4; r++) acc[i][j][r] = 0.0f;

    const uint4* Af = g_hf + (size_t)tt * HFT;

    for (int k0 = 0; k0 < H_; k0 += 16) {
        int ktb = k0 >> 3;
#pragma unroll
        for (int it = 0; it < 2; it++) {
            int idx = it * 256 + tid;
            Asf[idx] = Af[ktb * 256 + idx];
            int row = idx >> 2;
            int kq = (idx & 3) * 4;
            float4 v = *(const float4*)(Whr + (size_t)(bn + row) * H_ + k0 + kq);
            Bs[kq + 0][row] = f2tf(v.x); Bs[kq + 1][row] = f2tf(v.y);
            Bs[kq + 2][row] = f2tf(v.z); Bs[kq + 3][row] = f2tf(v.w);
        }
        __syncthreads();
#pragma unroll
        for (int k2 = 0; k2 < 2; k2++) {
            unsigned b[4][2];
#pragma unroll
            for (int j = 0; j < 4; j++) {
                int n = wn + j * 8;
                b[j][0] = Bs[k2 * 8 + c][n + g];
                b[j][1] = Bs[k2 * 8 + 4 + c][n + g];
            }
#pragma unroll
            for (int i = 0; i < 4; i++) {
                int mi = (wm >> 4) + i;
                uint4 av = Asf[(k2 * 8 + mi) * 32 + lane];
                unsigned a4[4] = {av.x, av.y, av.z, av.w};
#pragma unroll
                for (int j = 0; j < 4; j++) mma_tf32(acc[i][j], a4, b[j]);
            }
        }
        __syncthreads();
    }

#pragma unroll
    for (int i = 0; i < 4; i++) {
        int r0 = tt * 128 + wm + i * 16 + g;
#pragma unroll
        for (int j = 0; j < 4; j++) {
            int cc = bn + wn + j * 8 + c * 2;
            *(float2*)(out + (size_t)r0 * P_ + cc)       = make_float2(acc[i][j][0], acc[i][j][1]);
            *(float2*)(out + (size_t)(r0 + 8) * P_ + cc) = make_float2(acc[i][j][2], acc[i][j][3]);
        }
    }
}

// ---------------- hT = ys[T-1] ----------------
__global__ void tail_kernel(float* __restrict__ out) {
    int i = blockIdx.x * blockDim.x + threadIdx.x;
    if (i < B_ * P_)
        out[(size_t)T_ * B_ * P_ + i] = out[(size_t)(T_ * B_ - B_) * P_ + i];
}

// ---------------- launch ----------------
extern "C" void kernel_launch(void* const* d_in, const int* in_sizes, int n_in,
                              void* d_out, int out_size) {
    const float* x   = (const float*)d_in[0];   // [T,B,I]
    const float* h0  = (const float*)d_in[1];   // [1,B,P]
    const float* c0  = (const float*)d_in[2];   // [1,B,H]
    const float* Wih = (const float*)d_in[3];   // [4H,I]
    const float* Whh = (const float*)d_in[4];   // [4H,P]
    const float* Whr = (const float*)d_in[5];   // [P,H]
    float* out = (float*)d_out;                 // [ys | hT | cT]

    static int smem_set = 0;
    if (!smem_set) {
        cudaFuncSetAttribute(lstm_seq_kernel,
                             cudaFuncAttributeMaxDynamicSharedMemorySize, 204800);
        smem_set = 1;
    }

    init_kernel<<<1, 1024>>>();

    dim3 gx(G_ / 128, (T_ * B_) / 128);
    xg_mma_kernel<<<gx, 256>>>(x, Wih);
    fold0_mma_kernel<<<G_ / 128, 256>>>(h0, Whh);

    dim3 gw(H_ / 128, G_ / 128);
    wcomb_mma_kernel<<<gw, 256>>>(Whh, Whr);

    lstm_seq_kernel<<<NBLK, NTHR, 204800>>>(c0, out);

    dim3 gy(P_ / 128, T_);
    y_mma_kernel<<<gy, 256>>>(Whr, out);
    tail_kernel<<<(B_ * P_ + 255) / 256, 256>>>(out);
}